// round 6
// baseline (speedup 1.0000x reference)
#include <cuda_runtime.h>
#include <math.h>

#define H 128
#define NCHK 8000
#define NVAR 16000
#define EDGES 60000
#define NITER 10
#define LN_EPS 1e-6f

#define RT 64
#define XSTD 66
#define SMEM_BYTES (128 * 128 * 4 + 128 * XSTD * 8)   // 65536 + 67584 = 133120

typedef unsigned long long u64;

__device__ float g_hc[NCHK * H];
__device__ float g_hv[NVAR * H];
__device__ float g_P0c[NCHK * 256];
__device__ float g_P1c[NCHK * 256];
__device__ float g_P0v[NVAR * 256];
__device__ float g_P1v[NVAR * 256];
__device__ float g_aggc[NCHK * H];
__device__ float g_aggv[NVAR * H];
__device__ float g_updc[NCHK * H];
__device__ float g_updv[NVAR * H];
__device__ int g_cnt_c[NCHK], g_cnt_v[NVAR];
__device__ int g_rp_c[NCHK + 1], g_rp_v[NVAR + 1];
__device__ int g_cur_c[NCHK], g_cur_v[NVAR];
__device__ int g_el_c[EDGES], g_el_v[EDGES];

__device__ __forceinline__ float elu_f(float x) { return x > 0.f ? x : expm1f(x); }
__device__ __forceinline__ float sig_f(float x) { return 1.f / (1.f + expf(-x)); }

__device__ __forceinline__ u64 pack2(float lo, float hi) {
    u64 p; asm("mov.b64 %0, {%1, %2};" : "=l"(p) : "f"(lo), "f"(hi)); return p;
}
__device__ __forceinline__ void fma2(u64& d, u64 a, u64 b) {
    asm("fma.rn.f32x2 %0, %1, %2, %0;" : "+l"(d) : "l"(a), "l"(b));
}
__device__ __forceinline__ float2 unpack2(u64 p) {
    float2 r; asm("mov.b64 {%0, %1}, %2;" : "=f"(r.x), "=f"(r.y) : "l"(p)); return r;
}

// ---- GEMM blocks: 256 thr, cg=tid&15 -> cols 8cg..8cg+7, rg=tid>>4 -> rows 4rg..4rg+3
__device__ __forceinline__ void loadW(float* Ws, const float* __restrict__ W, int ld, int colOff, int tid)
{
    #pragma unroll
    for (int idx = tid; idx < 4096; idx += 256) {
        const int k = idx >> 5, cq = idx & 31;
        *(float4*)&Ws[k * 128 + 4 * cq] = *(const float4*)&W[(size_t)k * ld + colOff + 4 * cq];
    }
}
__device__ __forceinline__ void gather(float2* XsT, const float* __restrict__ A, int row0, int n, int tid)
{
    #pragma unroll
    for (int idx = tid; idx < RT * 128; idx += 256) {
        const int r = idx >> 7, k = idx & 127;
        int rr = row0 + r; if (rr >= n) rr = n - 1;
        const float v = A[(size_t)rr * 128 + k];
        XsT[k * XSTD + r] = make_float2(v, v);
    }
}
__device__ __forceinline__ void makeB(u64 bq[4], const float* __restrict__ b, int off, int cg)
{
    #pragma unroll
    for (int q = 0; q < 4; q++)
        bq[q] = b ? pack2(b[off + 8 * cg + 2 * q], b[off + 8 * cg + 2 * q + 1]) : 0ull;
}
template<bool INIT>
__device__ __forceinline__ void kloop(const float* Ws, const float2* XsT, int cg, int rg,
                                      u64 acc[4][4], const u64 bq[4])
{
    if (INIT) {
        #pragma unroll
        for (int p = 0; p < 4; p++)
            #pragma unroll
            for (int q = 0; q < 4; q++) acc[p][q] = bq[q];
    }
    #pragma unroll 4
    for (int k = 0; k < 128; k++) {
        const ulonglong2* xr = (const ulonglong2*)(XsT + k * XSTD + 4 * rg);
        const ulonglong2 x01 = xr[0], x23 = xr[1];
        const u64 xp[4] = {x01.x, x01.y, x23.x, x23.y};
        const ulonglong2* wr = (const ulonglong2*)(Ws + k * 128 + 8 * cg);
        const ulonglong2 w01 = wr[0], w23 = wr[1];
        const u64 wd[4] = {w01.x, w01.y, w23.x, w23.y};
        #pragma unroll
        for (int p = 0; p < 4; p++)
            #pragma unroll
            for (int q = 0; q < 4; q++) fma2(acc[p][q], xp[p], wd[q]);
    }
}
__device__ __forceinline__ void store8(float* o, const u64 a0, const u64 a1, const u64 a2, const u64 a3, bool act)
{
    const float2 v0 = unpack2(a0), v1 = unpack2(a1), v2 = unpack2(a2), v3 = unpack2(a3);
    float4 a, b;
    if (act) {
        a = make_float4(elu_f(v0.x), elu_f(v0.y), elu_f(v1.x), elu_f(v1.y));
        b = make_float4(elu_f(v2.x), elu_f(v2.y), elu_f(v3.x), elu_f(v3.y));
    } else {
        a = make_float4(v0.x, v0.y, v1.x, v1.y);
        b = make_float4(v2.x, v2.y, v3.x, v3.y);
    }
    *(float4*)o = a; *(float4*)(o + 4) = b;
}

struct NodeP {
    const float* PsendIn; const float* PtgtIn; float* Pout;
    float* h; float* agg; float* upd;
    const int* rowptr; const int* elist;
    const float* bmsg;
    const float* Wns; const float* bns;
    const float* Wg; const float* Ug; const float* bg;
    const float* Wms; const float* Wmr;
    int n;
};

__device__ __forceinline__ void tile_map(int b, int tilesC, bool& isC, int& tile)
{
    // tilesV == 2*tilesC for these sizes
    isC = (b % 3 == 0);
    tile = isC ? b / 3 : b - b / 3 - 1;
}

// ================= mega kernel: one launch per GNN iteration =================
__global__ void __launch_bounds__(256)
mega_kernel(NodeP C, NodeP V, int tilesC, int doMsg)
{
    extern __shared__ float sm[];
    float*  Ws  = sm;
    float2* XsT = (float2*)(sm + 128 * 128);
    const int tid = threadIdx.x;
    const int cg = tid & 15, rg = tid >> 4;

    bool isC; int tile;
    tile_map(blockIdx.x, tilesC, isC, tile);
    const NodeP& P = isC ? C : V;
    const int n = P.n;
    const int row0 = tile * RT;
    if (row0 >= n) return;

    // phase 0: aggregate (reads prev-iteration P buffers)
    {
        const int j = tid & 127, r0 = tid >> 7;
        const float bj = P.bmsg[j];
        for (int r = r0; r < RT; r += 2) {
            const int row = row0 + r;
            if (row >= n) break;
            const float base = P.PtgtIn[(size_t)row * 256 + 128 + j] + bj;
            const int beg = P.rowptr[row], end = P.rowptr[row + 1];
            float s0 = 0.f, s1 = 0.f;
            int i = beg;
            for (; i + 1 < end; i += 2) {
                s0 += elu_f(base + P.PsendIn[(size_t)P.elist[i]     * 256 + j]);
                s1 += elu_f(base + P.PsendIn[(size_t)P.elist[i + 1] * 256 + j]);
            }
            if (i < end) s0 += elu_f(base + P.PsendIn[(size_t)P.elist[i] * 256 + j]);
            P.agg[(size_t)row * 128 + j] = s0 + s1;
        }
    }

    u64 acc[4][4], bq[4];

    // S1: h @ Wns_top
    __syncthreads();
    loadW(Ws, P.Wns, 128, 0, tid);
    gather(XsT, P.h, row0, n, tid);
    __syncthreads();
    makeB(bq, P.bns, 0, cg);
    kloop<true>(Ws, XsT, cg, rg, acc, bq);

    // S2: + agg @ Wns_bot -> elu -> upd
    __syncthreads();
    loadW(Ws, P.Wns + 128 * 128, 128, 0, tid);
    gather(XsT, P.agg, row0, n, tid);
    __syncthreads();
    kloop<false>(Ws, XsT, cg, rg, acc, bq);
    #pragma unroll
    for (int p = 0; p < 4; p++) {
        const int row = row0 + 4 * rg + p;
        if (row < n) store8(P.upd + (size_t)row * 128 + 8 * cg,
                            acc[p][0], acc[p][1], acc[p][2], acc[p][3], true);
    }

    // S3-S5: xa gates (upd @ Wg)
    u64 xaz[4][4], xar[4][4], xah[4][4];
    __syncthreads();
    loadW(Ws, P.Wg, 384, 0, tid);
    gather(XsT, P.upd, row0, n, tid);
    __syncthreads();
    makeB(bq, P.bg, 0, cg);
    kloop<true>(Ws, XsT, cg, rg, xaz, bq);

    __syncthreads();
    loadW(Ws, P.Wg, 384, 128, tid);
    __syncthreads();
    makeB(bq, P.bg, 128, cg);
    kloop<true>(Ws, XsT, cg, rg, xar, bq);

    __syncthreads();
    loadW(Ws, P.Wg, 384, 256, tid);
    __syncthreads();
    makeB(bq, P.bg, 256, cg);
    kloop<true>(Ws, XsT, cg, rg, xah, bq);

    // S6: z = sig(xa_z + h @ Ug_z)
    __syncthreads();
    loadW(Ws, P.Ug, 384, 0, tid);
    gather(XsT, P.h, row0, n, tid);
    __syncthreads();
    makeB(bq, P.bg, 384, cg);
    kloop<true>(Ws, XsT, cg, rg, acc, bq);
    #pragma unroll
    for (int p = 0; p < 4; p++)
        #pragma unroll
        for (int q = 0; q < 4; q++) {
            const float2 xa_ = unpack2(xaz[p][q]);
            const float2 ha_ = unpack2(acc[p][q]);
            xaz[p][q] = pack2(sig_f(xa_.x + ha_.x), sig_f(xa_.y + ha_.y));  // xaz := z
        }

    // S7: r = sig(xa_r + h @ Ug_r)
    __syncthreads();
    loadW(Ws, P.Ug, 384, 128, tid);
    __syncthreads();
    makeB(bq, P.bg, 384 + 128, cg);
    kloop<true>(Ws, XsT, cg, rg, acc, bq);
    #pragma unroll
    for (int p = 0; p < 4; p++)
        #pragma unroll
        for (int q = 0; q < 4; q++) {
            const float2 xa_ = unpack2(xar[p][q]);
            const float2 ha_ = unpack2(acc[p][q]);
            xar[p][q] = pack2(sig_f(xa_.x + ha_.x), sig_f(xa_.y + ha_.y));  // xar := r
        }

    // S8: cand + combine -> h
    __syncthreads();
    loadW(Ws, P.Ug, 384, 256, tid);
    __syncthreads();
    makeB(bq, P.bg, 384 + 256, cg);
    kloop<true>(Ws, XsT, cg, rg, acc, bq);
    #pragma unroll
    for (int p = 0; p < 4; p++) {
        const int row = row0 + 4 * rg + p;
        if (row < n) {
            float* hrow = P.h + (size_t)row * 128 + 8 * cg;
            const float4 h0 = *(const float4*)hrow;
            const float4 h1 = *(const float4*)(hrow + 4);
            const float hold[8] = {h0.x, h0.y, h0.z, h0.w, h1.x, h1.y, h1.z, h1.w};
            float ov[8];
            #pragma unroll
            for (int q = 0; q < 4; q++) {
                const float2 xa_ = unpack2(xah[p][q]);
                const float2 ha_ = unpack2(acc[p][q]);
                const float2 zz = unpack2(xaz[p][q]);
                const float2 rr = unpack2(xar[p][q]);
                const float c0 = tanhf(xa_.x + rr.x * ha_.x);
                const float c1 = tanhf(xa_.y + rr.y * ha_.y);
                ov[2 * q]     = zz.x * hold[2 * q]     + (1.f - zz.x) * c0;
                ov[2 * q + 1] = zz.y * hold[2 * q + 1] + (1.f - zz.y) * c1;
            }
            *(float4*)hrow       = make_float4(ov[0], ov[1], ov[2], ov[3]);
            *(float4*)(hrow + 4) = make_float4(ov[4], ov[5], ov[6], ov[7]);
        }
    }

    // S9/S10: next-iteration message projections into Pout
    if (doMsg) {
        __syncthreads();
        loadW(Ws, P.Wms, 128, 0, tid);
        gather(XsT, P.h, row0, n, tid);
        __syncthreads();
        kloop<true>(Ws, XsT, cg, rg, acc, nullptr ? bq : (makeB(bq, nullptr, 0, cg), bq));
        #pragma unroll
        for (int p = 0; p < 4; p++) {
            const int row = row0 + 4 * rg + p;
            if (row < n) store8(P.Pout + (size_t)row * 256 + 8 * cg,
                                acc[p][0], acc[p][1], acc[p][2], acc[p][3], false);
        }
        __syncthreads();
        loadW(Ws, P.Wmr, 128, 0, tid);
        __syncthreads();
        kloop<true>(Ws, XsT, cg, rg, acc, bq);
        #pragma unroll
        for (int p = 0; p < 4; p++) {
            const int row = row0 + 4 * rg + p;
            if (row < n) store8(P.Pout + (size_t)row * 256 + 128 + 8 * cg,
                                acc[p][0], acc[p][1], acc[p][2], acc[p][3], false);
        }
    }
}

// ================= msg init: Pout = h @ [Wms | Wmr] =================
__global__ void __launch_bounds__(256)
msginit_kernel(NodeP C, NodeP V, int tilesC)
{
    extern __shared__ float sm[];
    float*  Ws  = sm;
    float2* XsT = (float2*)(sm + 128 * 128);
    const int tid = threadIdx.x;
    const int cg = tid & 15, rg = tid >> 4;

    bool isC; int tile;
    tile_map(blockIdx.x, tilesC, isC, tile);
    const NodeP& P = isC ? C : V;
    const int n = P.n;
    const int row0 = tile * RT;
    if (row0 >= n) return;

    u64 acc[4][4], bq[4];
    makeB(bq, nullptr, 0, cg);

    loadW(Ws, P.Wms, 128, 0, tid);
    gather(XsT, P.h, row0, n, tid);
    __syncthreads();
    kloop<true>(Ws, XsT, cg, rg, acc, bq);
    #pragma unroll
    for (int p = 0; p < 4; p++) {
        const int row = row0 + 4 * rg + p;
        if (row < n) store8(P.Pout + (size_t)row * 256 + 8 * cg,
                            acc[p][0], acc[p][1], acc[p][2], acc[p][3], false);
    }
    __syncthreads();
    loadW(Ws, P.Wmr, 128, 0, tid);
    __syncthreads();
    kloop<true>(Ws, XsT, cg, rg, acc, bq);
    #pragma unroll
    for (int p = 0; p < 4; p++) {
        const int row = row0 + 4 * rg + p;
        if (row < n) store8(P.Pout + (size_t)row * 256 + 128 + 8 * cg,
                            acc[p][0], acc[p][1], acc[p][2], acc[p][3], false);
    }
}

// ---------------- init (fused C+V): h = LN(0.1*feat*Win + bin); zero cnt ----------------
__global__ void init_kernel(const float* cf, const float* vf,
                            const float* Wc, const float* bc, const float* gc, const float* blc,
                            const float* Wv, const float* bv, const float* gv, const float* blv,
                            float* hc, float* hv, int* cntc, int* cntv, int NC)
{
    __shared__ float red[4], red2[4];
    const int b = blockIdx.x, j = threadIdx.x;
    const float* feat; const float* Win; const float* bin; const float* g; const float* bln;
    float* hp; int node;
    if (b < NC) { if (j == 0) cntc[b] = 0; feat = cf; Win = Wc; bin = bc; g = gc; bln = blc; hp = hc; node = b; }
    else { const int bb = b - NC; if (j == 0) cntv[bb] = 0; feat = vf; Win = Wv; bin = bv; g = gv; bln = blv; hp = hv; node = bb; }

    const float val = 0.1f * feat[node] * Win[j] + bin[j];
    float s = val;
    #pragma unroll
    for (int o = 16; o > 0; o >>= 1) s += __shfl_xor_sync(0xffffffff, s, o);
    if ((j & 31) == 0) red[j >> 5] = s;
    __syncthreads();
    const float m = (red[0] + red[1] + red[2] + red[3]) * (1.0f / 128.0f);
    const float d = val - m;
    float s2 = d * d;
    #pragma unroll
    for (int o = 16; o > 0; o >>= 1) s2 += __shfl_xor_sync(0xffffffff, s2, o);
    if ((j & 31) == 0) red2[j >> 5] = s2;
    __syncthreads();
    const float v = (red2[0] + red2[1] + red2[2] + red2[3]) * (1.0f / 128.0f);
    hp[(size_t)node * H + j] = g[j] * d * rsqrtf(v + LN_EPS) + bln[j];
}

// ---------------- CSR ----------------
__global__ void hist_kernel(const int* t1, int* c1, const int* t2, int* c2, int nE, int gHalf)
{
    int b = blockIdx.x;
    const int* tgt; int* cnt;
    if (b < gHalf) { tgt = t1; cnt = c1; } else { tgt = t2; cnt = c2; b -= gHalf; }
    const int e = b * blockDim.x + threadIdx.x;
    if (e < nE) atomicAdd(&cnt[tgt[e]], 1);
}

__device__ void scan_impl(const int* cnt, int* rowptr, int* cursor, int n)
{
    __shared__ int wsum[32];
    __shared__ int tot_s;
    const int tid = threadIdx.x, lane = tid & 31, w = tid >> 5;
    int carry = 0;
    for (int base = 0; base < n; base += 1024) {
        const int i = base + tid;
        int x = (i < n) ? cnt[i] : 0;
        int v = x;
        #pragma unroll
        for (int off = 1; off < 32; off <<= 1) {
            int t = __shfl_up_sync(0xffffffff, v, off);
            if (lane >= off) v += t;
        }
        if (lane == 31) wsum[w] = v;
        __syncthreads();
        if (w == 0) {
            int t = wsum[lane];
            #pragma unroll
            for (int off = 1; off < 32; off <<= 1) {
                int u = __shfl_up_sync(0xffffffff, t, off);
                if (lane >= off) t += u;
            }
            wsum[lane] = t;
            if (lane == 31) tot_s = t;
        }
        __syncthreads();
        const int incl = v + (w > 0 ? wsum[w - 1] : 0);
        if (i < n) { const int ex = carry + incl - x; rowptr[i] = ex; cursor[i] = ex; }
        carry += tot_s;
        __syncthreads();
    }
    if (tid == 0) rowptr[n] = carry;
}

__global__ void scan2_kernel(const int* cA, int* rA, int* uA, int nA,
                             const int* cB, int* rB, int* uB, int nB)
{
    if (blockIdx.x == 0) scan_impl(cA, rA, uA, nA);
    else                 scan_impl(cB, rB, uB, nB);
}

__global__ void fill_kernel(const int* s1, const int* t1, int* u1, int* l1,
                            const int* s2, const int* t2, int* u2, int* l2, int nE, int gHalf)
{
    int b = blockIdx.x;
    const int* src; const int* tgt; int* cur; int* list;
    if (b < gHalf) { src = s1; tgt = t1; cur = u1; list = l1; }
    else           { src = s2; tgt = t2; cur = u2; list = l2; b -= gHalf; }
    const int e = b * blockDim.x + threadIdx.x;
    if (e < nE) { const int p = atomicAdd(&cur[tgt[e]], 1); list[p] = src[e]; }
}

// ---------------- final ----------------
__global__ void final_kernel(const float* __restrict__ hv, const float* __restrict__ Wf,
                             const float* __restrict__ bf, float* __restrict__ out, int n)
{
    const int gw = (blockIdx.x * blockDim.x + threadIdx.x) >> 5;
    const int lane = threadIdx.x & 31;
    if (gw >= n) return;
    const float* row = hv + (size_t)gw * H;
    float s = row[lane] * Wf[lane] + row[lane + 32] * Wf[lane + 32]
            + row[lane + 64] * Wf[lane + 64] + row[lane + 96] * Wf[lane + 96];
    #pragma unroll
    for (int o = 16; o > 0; o >>= 1) s += __shfl_xor_sync(0xffffffff, s, o);
    if (lane == 0) out[gw] = s + bf[0];
}

// ---------------- host ----------------
extern "C" void kernel_launch(void* const* d_in, const int* in_sizes, int n_in,
                              void* d_out, int out_size)
{
    const float* check_feats = (const float*)d_in[0];
    const float* var_feats   = (const float*)d_in[1];
    const int*   c2v_src = (const int*)d_in[2];
    const int*   c2v_tgt = (const int*)d_in[3];
    const int*   v2c_src = (const int*)d_in[4];
    const int*   v2c_tgt = (const int*)d_in[5];
    const float* Wc_in = (const float*)d_in[6];
    const float* bc_in = (const float*)d_in[7];
    const float* Wv_in = (const float*)d_in[8];
    const float* bv_in = (const float*)d_in[9];
    const float* gc_ln = (const float*)d_in[10];
    const float* bc_ln = (const float*)d_in[11];
    const float* gv_ln = (const float*)d_in[12];
    const float* bv_ln = (const float*)d_in[13];
    const float* Wmsg_c = (const float*)d_in[14];
    const float* bmsg_c = (const float*)d_in[15];
    const float* Wmsg_v = (const float*)d_in[16];
    const float* bmsg_v = (const float*)d_in[17];
    const float* Wns_c = (const float*)d_in[18];
    const float* bns_c = (const float*)d_in[19];
    const float* Wns_v = (const float*)d_in[20];
    const float* bns_v = (const float*)d_in[21];
    const float* Wg_c = (const float*)d_in[22];
    const float* Ug_c = (const float*)d_in[23];
    const float* bg_c = (const float*)d_in[24];
    const float* Wg_v = (const float*)d_in[25];
    const float* Ug_v = (const float*)d_in[26];
    const float* bg_v = (const float*)d_in[27];
    const float* Wf = (const float*)d_in[28];
    const float* bf = (const float*)d_in[29];

    const int NCn = in_sizes[0];
    const int NVn = in_sizes[1];
    const int E   = in_sizes[2];

    float *hc, *hv, *P0c, *P1c, *P0v, *P1v, *aggc, *aggv, *updc, *updv;
    int *cnt_c, *cnt_v, *rp_c, *rp_v, *cur_c, *cur_v, *el_c, *el_v;
    cudaGetSymbolAddress((void**)&hc, g_hc);
    cudaGetSymbolAddress((void**)&hv, g_hv);
    cudaGetSymbolAddress((void**)&P0c, g_P0c);
    cudaGetSymbolAddress((void**)&P1c, g_P1c);
    cudaGetSymbolAddress((void**)&P0v, g_P0v);
    cudaGetSymbolAddress((void**)&P1v, g_P1v);
    cudaGetSymbolAddress((void**)&aggc, g_aggc);
    cudaGetSymbolAddress((void**)&aggv, g_aggv);
    cudaGetSymbolAddress((void**)&updc, g_updc);
    cudaGetSymbolAddress((void**)&updv, g_updv);
    cudaGetSymbolAddress((void**)&cnt_c, g_cnt_c);
    cudaGetSymbolAddress((void**)&cnt_v, g_cnt_v);
    cudaGetSymbolAddress((void**)&rp_c, g_rp_c);
    cudaGetSymbolAddress((void**)&rp_v, g_rp_v);
    cudaGetSymbolAddress((void**)&cur_c, g_cur_c);
    cudaGetSymbolAddress((void**)&cur_v, g_cur_v);
    cudaGetSymbolAddress((void**)&el_c, g_el_c);
    cudaGetSymbolAddress((void**)&el_v, g_el_v);

    cudaFuncSetAttribute(mega_kernel,    cudaFuncAttributeMaxDynamicSharedMemorySize, SMEM_BYTES);
    cudaFuncSetAttribute(msginit_kernel, cudaFuncAttributeMaxDynamicSharedMemorySize, SMEM_BYTES);

    const int tilesC = (NCn + RT - 1) / RT;   // 125
    const int tilesV = (NVn + RT - 1) / RT;   // 250
    const int grid = tilesC + tilesV;         // 375
    const int gEh = (E + 255) / 256;

    NodeP C, V;
    C.h = hc; C.agg = aggc; C.upd = updc;
    C.rowptr = rp_c; C.elist = el_c; C.bmsg = bmsg_c;
    C.Wns = Wns_c; C.bns = bns_c; C.Wg = Wg_c; C.Ug = Ug_c; C.bg = bg_c;
    C.Wms = Wmsg_v;              // c is sender on c2v edges: top half of Wmsg_v
    C.Wmr = Wmsg_c + 128 * 128;  // c is receiver on v2c edges: bottom half of Wmsg_c
    C.n = NCn;

    V.h = hv; V.agg = aggv; V.upd = updv;
    V.rowptr = rp_v; V.elist = el_v; V.bmsg = bmsg_v;
    V.Wns = Wns_v; V.bns = bns_v; V.Wg = Wg_v; V.Ug = Ug_v; V.bg = bg_v;
    V.Wms = Wmsg_c;              // v is sender on v2c edges
    V.Wmr = Wmsg_v + 128 * 128;  // v is receiver on c2v edges
    V.n = NVn;

    init_kernel<<<NCn + NVn, 128>>>(check_feats, var_feats,
                                    Wc_in, bc_in, gc_ln, bc_ln,
                                    Wv_in, bv_in, gv_ln, bv_ln,
                                    hc, hv, cnt_c, cnt_v, NCn);
    hist_kernel<<<2 * gEh, 256>>>(v2c_tgt, cnt_c, c2v_tgt, cnt_v, E, gEh);
    scan2_kernel<<<2, 1024>>>(cnt_c, rp_c, cur_c, NCn, cnt_v, rp_v, cur_v, NVn);
    fill_kernel<<<2 * gEh, 256>>>(v2c_src, v2c_tgt, cur_c, el_c,
                                  c2v_src, c2v_tgt, cur_v, el_v, E, gEh);

    // initial message projections into buffer 0
    C.Pout = P0c; V.Pout = P0v;
    msginit_kernel<<<grid, 256, SMEM_BYTES>>>(C, V, tilesC);

    for (int it = 0; it < NITER; it++) {
        const int cur = it & 1;
        // read buffer `cur`, write buffer `cur^1`
        C.PtgtIn = cur ? P1c : P0c;  C.PsendIn = cur ? P1v : P0v;  C.Pout = cur ? P0c : P1c;
        V.PtgtIn = cur ? P1v : P0v;  V.PsendIn = cur ? P1c : P0c;  V.Pout = cur ? P0v : P1v;
        mega_kernel<<<grid, 256, SMEM_BYTES>>>(C, V, tilesC, it + 1 < NITER ? 1 : 0);
    }

    final_kernel<<<(NVn * 32 + 127) / 128, 128>>>(hv, Wf, bf, (float*)d_out, NVn);
}

// round 7
// speedup vs baseline: 1.7014x; 1.7014x over previous
#include <cuda_runtime.h>
#include <math.h>

#define H 128
#define NCHK 8000
#define NVAR 16000
#define EDGES 60000
#define NITER 10
#define LN_EPS 1e-6f

#define RT 64
#define XSTD 66
#define SMEM_N (128 * 128 * 4 + 128 * XSTD * 8)       // 133,120
#define SMEM_K (2 * 128 * 128 * 4 + 128 * XSTD * 8)   // 198,656

typedef unsigned long long u64;

// ---------------- scratch ----------------
__device__ float g_hc[NCHK * H];
__device__ float g_hv[NVAR * H];
__device__ float g_Pc[NCHK * 256];
__device__ float g_Pv[NVAR * 256];
__device__ float g_aggc[NCHK * H];
__device__ float g_aggv[NVAR * H];
__device__ float g_updc[NCHK * H];
__device__ float g_updv[NVAR * H];
__device__ float g_xac[NCHK * 384];
__device__ float g_hac[NCHK * 384];
__device__ float g_xav[NVAR * 384];
__device__ float g_hav[NVAR * 384];
__device__ int g_cnt_c[NCHK], g_cnt_v[NVAR];
__device__ int g_rp_c[NCHK + 1], g_rp_v[NVAR + 1];
__device__ int g_cur_c[NCHK], g_cur_v[NVAR];
__device__ int g_el_c[EDGES], g_el_v[EDGES];

__device__ __forceinline__ float elu_f(float x) { return x > 0.f ? x : expm1f(x); }
__device__ __forceinline__ float sig_f(float x) { return 1.f / (1.f + expf(-x)); }

__device__ __forceinline__ u64 pack2(float lo, float hi) {
    u64 p; asm("mov.b64 %0, {%1, %2};" : "=l"(p) : "f"(lo), "f"(hi)); return p;
}
__device__ __forceinline__ void fma2(u64& d, u64 a, u64 b) {
    asm("fma.rn.f32x2 %0, %1, %2, %0;" : "+l"(d) : "l"(a), "l"(b));
}
__device__ __forceinline__ float2 unpack2(u64 p) {
    float2 r; asm("mov.b64 {%0, %1}, %2;" : "=f"(r.x), "=f"(r.y) : "l"(p)); return r;
}

// ================= GEMM building blocks =================
// 256 threads; cg=tid&15, rg=tid>>4. Thread computes rows 4rg..4rg+3 and
// cols {4cg..4cg+3} U {64+4cg..64+4cg+3}. W natural in SMEM (LDS.128 over a
// contiguous 256B window -> degree 2). X duplicated (x,x) -> broadcast reads.
__device__ __forceinline__ void loadW(float* Ws, const float* __restrict__ W, int ld, int tid)
{
    #pragma unroll
    for (int idx = tid; idx < 4096; idx += 256) {
        const int k = idx >> 5, cq = idx & 31;
        *(float4*)&Ws[k * 128 + 4 * cq] = *(const float4*)&W[(size_t)k * ld + 4 * cq];
    }
}
__device__ __forceinline__ void prefetchA(float v[32], const float* __restrict__ A,
                                          int row0, int n, int tid)
{
    #pragma unroll
    for (int i = 0; i < 32; i++) {
        const int idx = tid + (i << 8);
        int rr = row0 + (idx >> 7); if (rr >= n) rr = n - 1;
        v[i] = A[(size_t)rr * 128 + (idx & 127)];
    }
}
__device__ __forceinline__ void commitX(float2* XsT, const float v[32], int tid)
{
    #pragma unroll
    for (int i = 0; i < 32; i++) {
        const int idx = tid + (i << 8);
        XsT[(idx & 127) * XSTD + (idx >> 7)] = make_float2(v[i], v[i]);
    }
}
__device__ __forceinline__ void makeB(u64 bq[4], const float* __restrict__ b, int off, int cg)
{
    if (b) {
        bq[0] = pack2(b[off + 4 * cg],      b[off + 4 * cg + 1]);
        bq[1] = pack2(b[off + 4 * cg + 2],  b[off + 4 * cg + 3]);
        bq[2] = pack2(b[off + 64 + 4 * cg],     b[off + 64 + 4 * cg + 1]);
        bq[3] = pack2(b[off + 64 + 4 * cg + 2], b[off + 64 + 4 * cg + 3]);
    } else { bq[0] = bq[1] = bq[2] = bq[3] = 0ull; }
}
template<bool INIT>
__device__ __forceinline__ void kloop(const float* Ws, const float2* XsT, int cg, int rg,
                                      u64 acc[4][4], const u64 bq[4])
{
    if (INIT) {
        #pragma unroll
        for (int p = 0; p < 4; p++)
            #pragma unroll
            for (int q = 0; q < 4; q++) acc[p][q] = bq[q];
    }
    #pragma unroll 4
    for (int k = 0; k < 128; k++) {
        const ulonglong2* xr = (const ulonglong2*)(XsT + k * XSTD + 4 * rg);
        const ulonglong2 x01 = xr[0], x23 = xr[1];
        const u64 xp[4] = {x01.x, x01.y, x23.x, x23.y};
        const ulonglong2 wA = *(const ulonglong2*)(Ws + k * 128 + 4 * cg);
        const ulonglong2 wB = *(const ulonglong2*)(Ws + k * 128 + 64 + 4 * cg);
        const u64 wd[4] = {wA.x, wA.y, wB.x, wB.y};
        #pragma unroll
        for (int p = 0; p < 4; p++)
            #pragma unroll
            for (int q = 0; q < 4; q++) fma2(acc[p][q], xp[p], wd[q]);
    }
}
__device__ __forceinline__ void storeRow(float* o, u64 a0, u64 a1, u64 a2, u64 a3, bool act)
{
    const float2 v0 = unpack2(a0), v1 = unpack2(a1), v2 = unpack2(a2), v3 = unpack2(a3);
    float4 a, b;
    if (act) {
        a = make_float4(elu_f(v0.x), elu_f(v0.y), elu_f(v1.x), elu_f(v1.y));
        b = make_float4(elu_f(v2.x), elu_f(v2.y), elu_f(v3.x), elu_f(v3.y));
    } else {
        a = make_float4(v0.x, v0.y, v1.x, v1.y);
        b = make_float4(v2.x, v2.y, v3.x, v3.y);
    }
    *(float4*)o = a;
    *(float4*)(o + 64) = b;
}

// ---------- weight-stationary chunked GEMM (msg: NCH=2, gru: NCH=6) ----------
template<int NCH, bool ACT>
__global__ void __launch_bounds__(256, 1)
pgemmN_kernel(const float* __restrict__ A0, const float* __restrict__ A1,
              const float* __restrict__ Wa, const float* __restrict__ ba,
              const float* __restrict__ Wb, const float* __restrict__ bb,
              int ldw, int wstep,
              float* __restrict__ out0, float* __restrict__ out1,
              int outW, int nRows)
{
    extern __shared__ float sm[];
    float*  Ws  = sm;
    float2* XsT = (float2*)(sm + 128 * 128);
    const int tid = threadIdx.x;
    const int cg = tid & 15, rg = tid >> 4;

    constexpr int half = NCH / 2;
    const int c   = blockIdx.x % NCH;
    const int bpc = gridDim.x / NCH;
    const int t0  = blockIdx.x / NCH;
    const int sub = c % half;

    const float* A  = (c < half) ? A0 : A1;
    const float* W  = ((c < half) ? Wa : Wb) + (size_t)sub * wstep;
    const float* bp = (c < half) ? ba : bb;
    float*      out = (c < half) ? out0 : out1;

    loadW(Ws, W, ldw, tid);
    u64 bq[4];
    makeB(bq, bp, bp ? sub * 128 : 0, cg);

    const int nTiles = (nRows + RT - 1) / RT;
    if (t0 >= nTiles) return;

    float v[32];
    prefetchA(v, A, t0 * RT, nRows, tid);
    __syncthreads();               // Ws ready, XsT free
    commitX(XsT, v, tid);
    __syncthreads();

    for (int tile = t0; tile < nTiles; tile += bpc) {
        const int row0 = tile * RT;
        const int nxt = tile + bpc;
        if (nxt < nTiles) prefetchA(v, A, nxt * RT, nRows, tid);

        u64 acc[4][4];
        kloop<true>(Ws, XsT, cg, rg, acc, bq);

        #pragma unroll
        for (int p = 0; p < 4; p++) {
            const int row = row0 + 4 * rg + p;
            if (row < nRows)
                storeRow(out + (size_t)row * outW + sub * 128 + 4 * cg,
                         acc[p][0], acc[p][1], acc[p][2], acc[p][3], ACT);
        }
        __syncthreads();           // kloop done reading XsT
        if (nxt < nTiles) {
            commitX(XsT, v, tid);
            __syncthreads();
        }
    }
}

// ---------- node-update GEMM: out = elu(h @ Wtop + agg @ Wbot + b), both W halves resident ----------
__global__ void __launch_bounds__(256, 1)
pgemmK_kernel(const float* __restrict__ A0, const float* __restrict__ A1,
              const float* __restrict__ W, const float* __restrict__ bias,
              float* __restrict__ out, int nRows)
{
    extern __shared__ float sm[];
    float*  Ws0 = sm;
    float*  Ws1 = sm + 128 * 128;
    float2* XsT = (float2*)(sm + 2 * 128 * 128);
    const int tid = threadIdx.x;
    const int cg = tid & 15, rg = tid >> 4;

    loadW(Ws0, W, 128, tid);
    loadW(Ws1, W + 128 * 128, 128, tid);
    u64 bq[4];
    makeB(bq, bias, 0, cg);

    const int nTiles = (nRows + RT - 1) / RT;
    if ((int)blockIdx.x >= nTiles) return;

    float v[32];
    prefetchA(v, A0, blockIdx.x * RT, nRows, tid);
    __syncthreads();
    commitX(XsT, v, tid);
    __syncthreads();

    for (int tile = blockIdx.x; tile < nTiles; tile += gridDim.x) {
        const int row0 = tile * RT;
        // stage 0: h @ Wtop  (prefetch agg for same tile meanwhile)
        prefetchA(v, A1, row0, nRows, tid);
        u64 acc[4][4];
        kloop<true>(Ws0, XsT, cg, rg, acc, bq);
        __syncthreads();
        commitX(XsT, v, tid);
        __syncthreads();

        // stage 1: + agg @ Wbot  (prefetch next tile's h meanwhile)
        const int nxt = tile + gridDim.x;
        if (nxt < nTiles) prefetchA(v, A0, nxt * RT, nRows, tid);
        kloop<false>(Ws1, XsT, cg, rg, acc, bq);

        #pragma unroll
        for (int p = 0; p < 4; p++) {
            const int row = row0 + 4 * rg + p;
            if (row < nRows)
                storeRow(out + (size_t)row * 128 + 4 * cg,
                         acc[p][0], acc[p][1], acc[p][2], acc[p][3], true);
        }
        __syncthreads();
        if (nxt < nTiles) {
            commitX(XsT, v, tid);
            __syncthreads();
        }
    }
}

// ---------------- aggregate ----------------
__global__ void agg_kernel(const int* __restrict__ rowptr, const int* __restrict__ srcs,
                           const float* __restrict__ Psend, const float* __restrict__ Ptgt,
                           const float* __restrict__ bias, float* __restrict__ out)
{
    const int t = blockIdx.x;
    const int j = threadIdx.x;
    const float base = Ptgt[(size_t)t * 256 + 128 + j] + bias[j];
    const int beg = rowptr[t], end = rowptr[t + 1];
    float s0 = 0.f, s1 = 0.f;
    int i = beg;
    for (; i + 1 < end; i += 2) {
        const int a = srcs[i], b = srcs[i + 1];
        s0 += elu_f(base + Psend[(size_t)a * 256 + j]);
        s1 += elu_f(base + Psend[(size_t)b * 256 + j]);
    }
    if (i < end) s0 += elu_f(base + Psend[(size_t)srcs[i] * 256 + j]);
    out[(size_t)t * 128 + j] = s0 + s1;
}

// ---------------- GRU combine ----------------
__global__ void gru_combine_kernel(const float* __restrict__ xa, const float* __restrict__ ha,
                                   float* __restrict__ h, int nNodes)
{
    const int idx = blockIdx.x * blockDim.x + threadIdx.x;
    if (idx >= nNodes * 32) return;
    const int n = idx >> 5;
    const int q = (idx & 31) * 4;
    const float4 xz = *(const float4*)&xa[(size_t)n * 384 + q];
    const float4 xr = *(const float4*)&xa[(size_t)n * 384 + 128 + q];
    const float4 xh = *(const float4*)&xa[(size_t)n * 384 + 256 + q];
    const float4 hz = *(const float4*)&ha[(size_t)n * 384 + q];
    const float4 hr = *(const float4*)&ha[(size_t)n * 384 + 128 + q];
    const float4 hh = *(const float4*)&ha[(size_t)n * 384 + 256 + q];
    float4 ho = *(const float4*)&h[(size_t)n * 128 + q];

    float z, r, c;
    z = sig_f(xz.x + hz.x); r = sig_f(xr.x + hr.x); c = tanhf(xh.x + r * hh.x); ho.x = z * ho.x + (1.f - z) * c;
    z = sig_f(xz.y + hz.y); r = sig_f(xr.y + hr.y); c = tanhf(xh.y + r * hh.y); ho.y = z * ho.y + (1.f - z) * c;
    z = sig_f(xz.z + hz.z); r = sig_f(xr.z + hr.z); c = tanhf(xh.z + r * hh.z); ho.z = z * ho.z + (1.f - z) * c;
    z = sig_f(xz.w + hz.w); r = sig_f(xr.w + hr.w); c = tanhf(xh.w + r * hh.w); ho.w = z * ho.w + (1.f - z) * c;
    *(float4*)&h[(size_t)n * 128 + q] = ho;
}

// ---------------- init (fused C+V) ----------------
__global__ void init_kernel(const float* cf, const float* vf,
                            const float* Wc, const float* bc, const float* gc, const float* blc,
                            const float* Wv, const float* bv, const float* gv, const float* blv,
                            float* hc, float* hv, int* cntc, int* cntv, int NC)
{
    __shared__ float red[4], red2[4];
    const int b = blockIdx.x, j = threadIdx.x;
    const float* feat; const float* Win; const float* bin; const float* g; const float* bln;
    float* hp; int node;
    if (b < NC) { if (j == 0) cntc[b] = 0; feat = cf; Win = Wc; bin = bc; g = gc; bln = blc; hp = hc; node = b; }
    else { const int bb = b - NC; if (j == 0) cntv[bb] = 0; feat = vf; Win = Wv; bin = bv; g = gv; bln = blv; hp = hv; node = bb; }

    const float val = 0.1f * feat[node] * Win[j] + bin[j];
    float s = val;
    #pragma unroll
    for (int o = 16; o > 0; o >>= 1) s += __shfl_xor_sync(0xffffffff, s, o);
    if ((j & 31) == 0) red[j >> 5] = s;
    __syncthreads();
    const float m = (red[0] + red[1] + red[2] + red[3]) * (1.0f / 128.0f);
    const float d = val - m;
    float s2 = d * d;
    #pragma unroll
    for (int o = 16; o > 0; o >>= 1) s2 += __shfl_xor_sync(0xffffffff, s2, o);
    if ((j & 31) == 0) red2[j >> 5] = s2;
    __syncthreads();
    const float v = (red2[0] + red2[1] + red2[2] + red2[3]) * (1.0f / 128.0f);
    hp[(size_t)node * H + j] = g[j] * d * rsqrtf(v + LN_EPS) + bln[j];
}

// ---------------- CSR (fused pairs) ----------------
__global__ void hist_kernel(const int* t1, int* c1, const int* t2, int* c2, int nE, int gHalf)
{
    int b = blockIdx.x;
    const int* tgt; int* cnt;
    if (b < gHalf) { tgt = t1; cnt = c1; } else { tgt = t2; cnt = c2; b -= gHalf; }
    const int e = b * blockDim.x + threadIdx.x;
    if (e < nE) atomicAdd(&cnt[tgt[e]], 1);
}

__device__ void scan_impl(const int* cnt, int* rowptr, int* cursor, int n)
{
    __shared__ int wsum[32];
    __shared__ int tot_s;
    const int tid = threadIdx.x, lane = tid & 31, w = tid >> 5;
    int carry = 0;
    for (int base = 0; base < n; base += 1024) {
        const int i = base + tid;
        int x = (i < n) ? cnt[i] : 0;
        int v = x;
        #pragma unroll
        for (int off = 1; off < 32; off <<= 1) {
            int t = __shfl_up_sync(0xffffffff, v, off);
            if (lane >= off) v += t;
        }
        if (lane == 31) wsum[w] = v;
        __syncthreads();
        if (w == 0) {
            int t = wsum[lane];
            #pragma unroll
            for (int off = 1; off < 32; off <<= 1) {
                int u = __shfl_up_sync(0xffffffff, t, off);
                if (lane >= off) t += u;
            }
            wsum[lane] = t;
            if (lane == 31) tot_s = t;
        }
        __syncthreads();
        const int incl = v + (w > 0 ? wsum[w - 1] : 0);
        if (i < n) { const int ex = carry + incl - x; rowptr[i] = ex; cursor[i] = ex; }
        carry += tot_s;
        __syncthreads();
    }
    if (tid == 0) rowptr[n] = carry;
}

__global__ void scan2_kernel(const int* cA, int* rA, int* uA, int nA,
                             const int* cB, int* rB, int* uB, int nB)
{
    if (blockIdx.x == 0) scan_impl(cA, rA, uA, nA);
    else                 scan_impl(cB, rB, uB, nB);
}

__global__ void fill_kernel(const int* s1, const int* t1, int* u1, int* l1,
                            const int* s2, const int* t2, int* u2, int* l2, int nE, int gHalf)
{
    int b = blockIdx.x;
    const int* src; const int* tgt; int* cur; int* list;
    if (b < gHalf) { src = s1; tgt = t1; cur = u1; list = l1; }
    else           { src = s2; tgt = t2; cur = u2; list = l2; b -= gHalf; }
    const int e = b * blockDim.x + threadIdx.x;
    if (e < nE) { const int p = atomicAdd(&cur[tgt[e]], 1); list[p] = src[e]; }
}

// ---------------- final ----------------
__global__ void final_kernel(const float* __restrict__ hv, const float* __restrict__ Wf,
                             const float* __restrict__ bf, float* __restrict__ out, int n)
{
    const int gw = (blockIdx.x * blockDim.x + threadIdx.x) >> 5;
    const int lane = threadIdx.x & 31;
    if (gw >= n) return;
    const float* row = hv + (size_t)gw * H;
    float s = row[lane] * Wf[lane] + row[lane + 32] * Wf[lane + 32]
            + row[lane + 64] * Wf[lane + 64] + row[lane + 96] * Wf[lane + 96];
    #pragma unroll
    for (int o = 16; o > 0; o >>= 1) s += __shfl_xor_sync(0xffffffff, s, o);
    if (lane == 0) out[gw] = s + bf[0];
}

// ---------------- host ----------------
static inline int mini(int a, int b) { return a < b ? a : b; }

extern "C" void kernel_launch(void* const* d_in, const int* in_sizes, int n_in,
                              void* d_out, int out_size)
{
    const float* check_feats = (const float*)d_in[0];
    const float* var_feats   = (const float*)d_in[1];
    const int*   c2v_src = (const int*)d_in[2];
    const int*   c2v_tgt = (const int*)d_in[3];
    const int*   v2c_src = (const int*)d_in[4];
    const int*   v2c_tgt = (const int*)d_in[5];
    const float* Wc_in = (const float*)d_in[6];
    const float* bc_in = (const float*)d_in[7];
    const float* Wv_in = (const float*)d_in[8];
    const float* bv_in = (const float*)d_in[9];
    const float* gc_ln = (const float*)d_in[10];
    const float* bc_ln = (const float*)d_in[11];
    const float* gv_ln = (const float*)d_in[12];
    const float* bv_ln = (const float*)d_in[13];
    const float* Wmsg_c = (const float*)d_in[14];
    const float* bmsg_c = (const float*)d_in[15];
    const float* Wmsg_v = (const float*)d_in[16];
    const float* bmsg_v = (const float*)d_in[17];
    const float* Wns_c = (const float*)d_in[18];
    const float* bns_c = (const float*)d_in[19];
    const float* Wns_v = (const float*)d_in[20];
    const float* bns_v = (const float*)d_in[21];
    const float* Wg_c = (const float*)d_in[22];
    const float* Ug_c = (const float*)d_in[23];
    const float* bg_c = (const float*)d_in[24];
    const float* Wg_v = (const float*)d_in[25];
    const float* Ug_v = (const float*)d_in[26];
    const float* bg_v = (const float*)d_in[27];
    const float* Wf = (const float*)d_in[28];
    const float* bf = (const float*)d_in[29];

    const int NCn = in_sizes[0];
    const int NVn = in_sizes[1];
    const int E   = in_sizes[2];

    float *hc, *hv, *Pc, *Pv, *aggc, *aggv, *updc, *updv, *xac, *hac, *xav, *hav;
    int *cnt_c, *cnt_v, *rp_c, *rp_v, *cur_c, *cur_v, *el_c, *el_v;
    cudaGetSymbolAddress((void**)&hc, g_hc);
    cudaGetSymbolAddress((void**)&hv, g_hv);
    cudaGetSymbolAddress((void**)&Pc, g_Pc);
    cudaGetSymbolAddress((void**)&Pv, g_Pv);
    cudaGetSymbolAddress((void**)&aggc, g_aggc);
    cudaGetSymbolAddress((void**)&aggv, g_aggv);
    cudaGetSymbolAddress((void**)&updc, g_updc);
    cudaGetSymbolAddress((void**)&updv, g_updv);
    cudaGetSymbolAddress((void**)&xac, g_xac);
    cudaGetSymbolAddress((void**)&hac, g_hac);
    cudaGetSymbolAddress((void**)&xav, g_xav);
    cudaGetSymbolAddress((void**)&hav, g_hav);
    cudaGetSymbolAddress((void**)&cnt_c, g_cnt_c);
    cudaGetSymbolAddress((void**)&cnt_v, g_cnt_v);
    cudaGetSymbolAddress((void**)&rp_c, g_rp_c);
    cudaGetSymbolAddress((void**)&rp_v, g_rp_v);
    cudaGetSymbolAddress((void**)&cur_c, g_cur_c);
    cudaGetSymbolAddress((void**)&cur_v, g_cur_v);
    cudaGetSymbolAddress((void**)&el_c, g_el_c);
    cudaGetSymbolAddress((void**)&el_v, g_el_v);

    auto msgGemm  = pgemmN_kernel<2, false>;
    auto gruGemm  = pgemmN_kernel<6, false>;
    cudaFuncSetAttribute(msgGemm, cudaFuncAttributeMaxDynamicSharedMemorySize, SMEM_N);
    cudaFuncSetAttribute(gruGemm, cudaFuncAttributeMaxDynamicSharedMemorySize, SMEM_N);
    cudaFuncSetAttribute(pgemmK_kernel, cudaFuncAttributeMaxDynamicSharedMemorySize, SMEM_K);

    const int tV = (NVn + RT - 1) / RT, tC = (NCn + RT - 1) / RT;
    const int gMsgV = 2 * mini(tV, 74), gMsgC = 2 * mini(tC, 74);
    const int gGruV = 6 * mini(tV, 24), gGruC = 6 * mini(tC, 24);
    const int gNodeV = mini(tV, 148),   gNodeC = mini(tC, 148);
    const int gEh = (E + 255) / 256;

    init_kernel<<<NCn + NVn, 128>>>(check_feats, var_feats,
                                    Wc_in, bc_in, gc_ln, bc_ln,
                                    Wv_in, bv_in, gv_ln, bv_ln,
                                    hc, hv, cnt_c, cnt_v, NCn);
    hist_kernel<<<2 * gEh, 256>>>(v2c_tgt, cnt_c, c2v_tgt, cnt_v, E, gEh);
    scan2_kernel<<<2, 1024>>>(cnt_c, rp_c, cur_c, NCn, cnt_v, rp_v, cur_v, NVn);
    fill_kernel<<<2 * gEh, 256>>>(v2c_src, v2c_tgt, cur_c, el_c,
                                  c2v_src, c2v_tgt, cur_v, el_v, E, gEh);

    for (int it = 0; it < NITER; it++) {
        // Pv[:,0:128]=hv@Wmsg_c_top (sender v2c); Pv[:,128:256]=hv@Wmsg_v_bot (receiver c2v)
        msgGemm<<<gMsgV, 256, SMEM_N>>>(
            hv, hv, Wmsg_c, nullptr, Wmsg_v + 128 * 128, nullptr,
            128, 0, Pv, Pv + 128, 256, NVn);
        msgGemm<<<gMsgC, 256, SMEM_N>>>(
            hc, hc, Wmsg_v, nullptr, Wmsg_c + 128 * 128, nullptr,
            128, 0, Pc, Pc + 128, 256, NCn);

        agg_kernel<<<NCn, 128>>>(rp_c, el_c, Pv, Pc, bmsg_c, aggc);
        agg_kernel<<<NVn, 128>>>(rp_v, el_v, Pc, Pv, bmsg_v, aggv);

        pgemmK_kernel<<<gNodeC, 256, SMEM_K>>>(hc, aggc, Wns_c, bns_c, updc, NCn);
        pgemmK_kernel<<<gNodeV, 256, SMEM_K>>>(hv, aggv, Wns_v, bns_v, updv, NVn);

        gruGemm<<<gGruC, 256, SMEM_N>>>(
            updc, hc, Wg_c, bg_c, Ug_c, bg_c + 384,
            384, 128, xac, hac, 384, NCn);
        gru_combine_kernel<<<(NCn * 32 + 255) / 256, 256>>>(xac, hac, hc, NCn);

        gruGemm<<<gGruV, 256, SMEM_N>>>(
            updv, hv, Wg_v, bg_v, Ug_v, bg_v + 384,
            384, 128, xav, hav, 384, NVn);
        gru_combine_kernel<<<(NVn * 32 + 255) / 256, 256>>>(xav, hav, hv, NVn);
    }

    final_kernel<<<(NVn * 32 + 127) / 128, 128>>>(hv, Wf, bf, (float*)d_out, NVn);
}